// round 2
// baseline (speedup 1.0000x reference)
#include <cuda_runtime.h>
#include <math.h>

// Problem constants
#define BATCH 32
#define CIN   8
#define COUT  8
#define KK    4
#define DIN   16
#define DOUT  16
#define SS    32
#define EPSV  1e-5f

// ---------------- scratch (device globals; no runtime alloc allowed) ------
// votes: [b][oc][y][x], oc = c*128 + o*16 + d  (134 MB)
__device__ float g_votes[(size_t)BATCH * 1024 * 1024];
// pooled: [b][o][p(2)][d][y][x]
__device__ float g_pooled[(size_t)BATCH * COUT * 2 * DOUT * SS * SS];
// routed: [b][o][d][y][x]  (pre-gate routing result)
__device__ float g_routed[(size_t)BATCH * COUT * DOUT * SS * SS];
// gate conv output pre-BN
__device__ float g_graw[(size_t)BATCH * COUT * DOUT * SS * SS];
__device__ double g_bnsum[COUT];
__device__ double g_bnsq[COUT];
__device__ float  g_bnmu[COUT];
__device__ float  g_bninv[COUT];

// ---------------- kernel 0: zero BN accumulators --------------------------
__global__ void k_zero_bn() {
    int i = threadIdx.x;
    if (i < COUT) { g_bnsum[i] = 0.0; g_bnsq[i] = 0.0; }
}

// ---------------- kernel 1: 3x3 conv (16 -> 1024 ch), pad 1 ---------------
// CTA = (oc_chunk of 64, batch).  256 threads.
// smem: padded input [16][34][35-stride], transposed weights [144][64], bias.
#define CONV_OC   64
#define IN_RS     35
#define IN_PLANE  (34 * IN_RS)          // 1190
#define SM_IN_F   (16 * IN_PLANE)       // 19040 floats
#define SM_W_F    (144 * CONV_OC)       // 9216 floats
#define CONV_SMEM ((SM_IN_F + SM_W_F + CONV_OC) * 4)

__global__ __launch_bounds__(256, 2) void k_conv(
    const float* __restrict__ caps,
    const float* __restrict__ Wt,
    const float* __restrict__ bt)
{
    extern __shared__ float sm[];
    float* smin = sm;
    float* smw  = sm + SM_IN_F;
    float* smb  = smw + SM_W_F;

    int b = blockIdx.y;
    int oc_base = blockIdx.x * CONV_OC;
    int tid = threadIdx.x;

    // load input with zero padding
    const float* cin = caps + (size_t)b * (DIN * SS * SS);
    for (int idx = tid; idx < 16 * 34 * 34; idx += 256) {
        int ch = idx / (34 * 34);
        int r  = (idx / 34) % 34;
        int c  = idx % 34;
        float v = 0.f;
        if (r >= 1 && r <= 32 && c >= 1 && c <= 32)
            v = cin[ch * 1024 + (r - 1) * 32 + (c - 1)];
        smin[ch * IN_PLANE + r * IN_RS + c] = v;
    }
    // load weights transposed: smw[t][ocl]
    for (int idx = tid; idx < SM_W_F; idx += 256) {
        int t = idx >> 6;
        int ocl = idx & 63;
        smw[idx] = Wt[(size_t)(oc_base + ocl) * 144 + t];
    }
    if (tid < CONV_OC) smb[tid] = bt[oc_base + tid];
    __syncthreads();

    int ocg  = tid >> 5;           // warp id 0..7 -> 8 oc per warp
    int lane = tid & 31;
    int x0   = (lane & 7) * 4;     // x quad base
    int ysub = lane >> 3;          // 0..3

    const float4* smw4 = (const float4*)smw;
    float bias[8];
#pragma unroll
    for (int oo = 0; oo < 8; oo++) bias[oo] = smb[ocg * 8 + oo];

    for (int ystep = 0; ystep < 8; ystep++) {
        int y = ystep * 4 + ysub;
        float acc[8][4];
#pragma unroll
        for (int oo = 0; oo < 8; oo++)
#pragma unroll
            for (int j = 0; j < 4; j++) acc[oo][j] = 0.f;

#pragma unroll 2
        for (int ic = 0; ic < 16; ic++) {
#pragma unroll
            for (int ky = 0; ky < 3; ky++) {
                const float* rp = &smin[ic * IN_PLANE + (y + ky) * IN_RS + x0];
                float in6[6];
#pragma unroll
                for (int j = 0; j < 6; j++) in6[j] = rp[j];
#pragma unroll
                for (int kx = 0; kx < 3; kx++) {
                    int t = ic * 9 + ky * 3 + kx;
                    float4 wa = smw4[t * 16 + ocg * 2];
                    float4 wb = smw4[t * 16 + ocg * 2 + 1];
#pragma unroll
                    for (int j = 0; j < 4; j++) {
                        float iv = in6[kx + j];
                        acc[0][j] += wa.x * iv;
                        acc[1][j] += wa.y * iv;
                        acc[2][j] += wa.z * iv;
                        acc[3][j] += wa.w * iv;
                        acc[4][j] += wb.x * iv;
                        acc[5][j] += wb.y * iv;
                        acc[6][j] += wb.z * iv;
                        acc[7][j] += wb.w * iv;
                    }
                }
            }
        }
#pragma unroll
        for (int oo = 0; oo < 8; oo++) {
            int oc = oc_base + ocg * 8 + oo;
            float4 r;
            r.x = acc[oo][0] + bias[oo];
            r.y = acc[oo][1] + bias[oo];
            r.z = acc[oo][2] + bias[oo];
            r.w = acc[oo][3] + bias[oo];
            *(float4*)&g_votes[((size_t)b * 1024 + oc) * 1024 + y * 32 + x0] = r;
        }
    }
}

// ---------------- kernel 2: einsum + pooling + routing ---------------------
// CTA: (siteblock, o, b). thread = one site, loops over d.
__global__ __launch_bounds__(256) void k_values(
    const float* __restrict__ Wv,
    const float* __restrict__ bv)
{
    __shared__ float sWv[COUT == 8 ? 256 : 256];   // 32 m x 8 c
    __shared__ float sbv[32];
    int b = blockIdx.z, o = blockIdx.y;
    int s = blockIdx.x * 256 + threadIdx.x;
    if (threadIdx.x < 256) sWv[threadIdx.x] = Wv[o * 256 + threadIdx.x];
    if (threadIdx.x < 32)  sbv[threadIdx.x] = bv[o * 32 + threadIdx.x];
    __syncthreads();

    const float* vb = g_votes + (size_t)b * 1048576 + (size_t)o * 16384 + s;
    size_t pbase = ((size_t)b * 8 + o) * 32768;       // pooled base
    size_t rbase = ((size_t)b * 8 + o) * 16384;       // routed base

    for (int d = 0; d < 16; d++) {
        float vc[8];
#pragma unroll
        for (int c = 0; c < 8; c++) vc[c] = vb[(size_t)(c * 128 + d) * 1024];

        float pmax = -3.0e38f, psum = 0.f;
        float mcin[8], li[8];
#pragma unroll
        for (int cin = 0; cin < 8; cin++) {
            float vals[4];
#pragma unroll
            for (int kc = 0; kc < 4; kc++) {
                int m = kc * 8 + cin;
                float a = sbv[m];
#pragma unroll
                for (int c = 0; c < 8; c++) a += sWv[m * 8 + c] * vc[c];
                vals[kc] = a;
                pmax = fmaxf(pmax, a);
                psum += a;
            }
            float mn = 0.25f * (vals[0] + vals[1] + vals[2] + vals[3]);
            float d0 = vals[0] - mn, d1 = vals[1] - mn, d2 = vals[2] - mn, d3 = vals[3] - mn;
            float var = 0.25f * (d0 * d0 + d1 * d1 + d2 * d2 + d3 * d3);
            float sd = sqrtf(var);
            mcin[cin] = mn;
            li[cin] = -logf(fmaxf(sd, 1e-30f));
        }
        // softmax over cin of li, weighted sum of means
        float mx = li[0];
#pragma unroll
        for (int c = 1; c < 8; c++) mx = fmaxf(mx, li[c]);
        float sum = 0.f, r = 0.f;
#pragma unroll
        for (int c = 0; c < 8; c++) {
            float e = expf(li[c] - mx);
            sum += e;
            r += e * mcin[c];
        }
        r /= sum;

        g_pooled[pbase + d * 1024 + s]         = pmax;
        g_pooled[pbase + 16384 + d * 1024 + s] = psum * (1.f / 32.f);
        g_routed[rbase + d * 1024 + s]         = r;
    }
}

// ---------------- kernel 3: 3x3x3 gate conv + BN partial sums --------------
// CTA per (b,o) = 256 blocks, 512 threads. smem holds full pooled[b][o].
__global__ __launch_bounds__(512) void k_gate(const float* __restrict__ Ws)
{
    extern __shared__ float sp[];           // 2*16*32*32 = 32768 floats
    __shared__ float sws[54];
    __shared__ double redA[16], redB[16];
    int blk = blockIdx.x;
    int o = blk & 7;
    int tid = threadIdx.x;

    const float* src = g_pooled + (size_t)blk * 32768;
    for (int i = tid; i < 32768; i += 512) sp[i] = src[i];
    if (tid < 54) sws[tid] = Ws[tid];
    __syncthreads();

    double ls = 0.0, lq = 0.0;
    for (int k = 0; k < 32; k++) {
        int idx = k * 512 + tid;
        int d = idx >> 10;
        int rm = idx & 1023;
        int u = rm >> 5, v = rm & 31;
        float a = 0.f;
#pragma unroll
        for (int p = 0; p < 2; p++) {
#pragma unroll
            for (int kd = 0; kd < 3; kd++) {
                int dd = d + kd - 1;
                if ((unsigned)dd >= 16u) continue;
#pragma unroll
                for (int ku = 0; ku < 3; ku++) {
                    int uu = u + ku - 1;
                    if ((unsigned)uu >= 32u) continue;
#pragma unroll
                    for (int kv = 0; kv < 3; kv++) {
                        int vv = v + kv - 1;
                        if ((unsigned)vv >= 32u) continue;
                        a += sp[p * 16384 + dd * 1024 + uu * 32 + vv] *
                             sws[p * 27 + kd * 9 + ku * 3 + kv];
                    }
                }
            }
        }
        g_graw[(size_t)blk * 16384 + idx] = a;
        ls += a;
        lq += (double)a * a;
    }
    // block reduce (fp64) then one atomic per block
    for (int off = 16; off; off >>= 1) {
        ls += __shfl_down_sync(0xffffffffu, ls, off);
        lq += __shfl_down_sync(0xffffffffu, lq, off);
    }
    int wid = tid >> 5, lane = tid & 31;
    if (lane == 0) { redA[wid] = ls; redB[wid] = lq; }
    __syncthreads();
    if (tid < 32) {
        double a = (tid < 16) ? redA[tid] : 0.0;
        double q = (tid < 16) ? redB[tid] : 0.0;
        for (int off = 8; off; off >>= 1) {
            a += __shfl_down_sync(0xffffffffu, a, off);
            q += __shfl_down_sync(0xffffffffu, q, off);
        }
        if (tid == 0) {
            atomicAdd(&g_bnsum[o], a);
            atomicAdd(&g_bnsq[o], q);
        }
    }
}

// ---------------- kernel 4: BN finalize ------------------------------------
__global__ void k_bnfin() {
    int o = threadIdx.x;
    if (o < COUT) {
        double N = (double)BATCH * DOUT * SS * SS;   // 524288
        double mu = g_bnsum[o] / N;
        double var = g_bnsq[o] / N - mu * mu;
        g_bnmu[o]  = (float)mu;
        g_bninv[o] = (float)(1.0 / sqrt(var + (double)EPSV));
    }
}

// ---------------- kernel 5: scale + LayerNorm + transposed store -----------
__global__ __launch_bounds__(512) void k_final(
    const float* __restrict__ bng, const float* __restrict__ bnb,
    const float* __restrict__ lng, const float* __restrict__ lnb,
    float* __restrict__ out)
{
    __shared__ double redA[16], redB[16];
    __shared__ float bc[2];
    int blk = blockIdx.x;
    int b = blk >> 3, o = blk & 7;
    int tid = threadIdx.x;

    float mu = g_bnmu[o], inv = g_bninv[o];
    float ga = bng[0], be = bnb[0];
    const float* gr = g_graw  + (size_t)blk * 16384;
    const float* rt = g_routed + (size_t)blk * 16384;

    double ls = 0.0, lq = 0.0;
    for (int k = 0; k < 32; k++) {
        int i = k * 512 + tid;
        float g = (gr[i] - mu) * inv * ga + be;
        float sc = 1.f / (1.f + expf(-g));
        float x = rt[i] * (1.f + sc);
        ls += x;
        lq += (double)x * x;
    }
    for (int off = 16; off; off >>= 1) {
        ls += __shfl_down_sync(0xffffffffu, ls, off);
        lq += __shfl_down_sync(0xffffffffu, lq, off);
    }
    int wid = tid >> 5, lane = tid & 31;
    if (lane == 0) { redA[wid] = ls; redB[wid] = lq; }
    __syncthreads();
    if (tid < 32) {
        double a = (tid < 16) ? redA[tid] : 0.0;
        double q = (tid < 16) ? redB[tid] : 0.0;
        for (int off = 8; off; off >>= 1) {
            a += __shfl_down_sync(0xffffffffu, a, off);
            q += __shfl_down_sync(0xffffffffu, q, off);
        }
        if (tid == 0) {
            double N = 16384.0;
            double mean = a / N;
            double var = q / N - mean * mean;
            bc[0] = (float)mean;
            bc[1] = (float)(1.0 / sqrt(var + (double)EPSV));
        }
    }
    __syncthreads();
    float mean = bc[0], rstd = bc[1];
    float* ob = out + ((size_t)o * BATCH + b) * 16384;
    for (int k = 0; k < 32; k++) {
        int i = k * 512 + tid;
        float g = (gr[i] - mu) * inv * ga + be;
        float x = rt[i] * (1.f + 1.f / (1.f + expf(-g)));
        ob[i] = (x - mean) * rstd * lng[i] + lnb[i];
    }
}

// ---------------- launch ----------------------------------------------------
extern "C" void kernel_launch(void* const* d_in, const int* in_sizes, int n_in,
                              void* d_out, int out_size)
{
    const float* caps = (const float*)d_in[0];
    const float* Wt   = (const float*)d_in[1];
    const float* bt   = (const float*)d_in[2];
    const float* Wv   = (const float*)d_in[3];
    const float* bv   = (const float*)d_in[4];
    const float* Ws   = (const float*)d_in[5];
    const float* bng  = (const float*)d_in[6];
    const float* bnb  = (const float*)d_in[7];
    const float* lng  = (const float*)d_in[8];
    const float* lnb  = (const float*)d_in[9];
    float* out = (float*)d_out;

    cudaFuncSetAttribute(k_conv, cudaFuncAttributeMaxDynamicSharedMemorySize, CONV_SMEM);
    cudaFuncSetAttribute(k_gate, cudaFuncAttributeMaxDynamicSharedMemorySize, 32768 * 4);

    k_zero_bn<<<1, 32>>>();

    dim3 gconv(1024 / CONV_OC, BATCH);               // (16, 32)
    k_conv<<<gconv, 256, CONV_SMEM>>>(caps, Wt, bt);

    dim3 gval(4, COUT, BATCH);                       // 1024 sites / 256 thr
    k_values<<<gval, 256>>>(Wv, bv);

    k_gate<<<BATCH * COUT, 512, 32768 * 4>>>(Ws);

    k_bnfin<<<1, 8>>>();

    k_final<<<BATCH * COUT, 512>>>(bng, bnb, lng, lnb, out);

    (void)in_sizes; (void)n_in; (void)out_size;
}

// round 3
// speedup vs baseline: 1.2041x; 1.2041x over previous
#include <cuda_runtime.h>
#include <math.h>

// Problem constants
#define BATCH 32
#define CIN   8
#define COUT  8
#define KK    4
#define DIN   16
#define DOUT  16
#define SS    32
#define EPSV  1e-5f

// ---------------- scratch (device globals; no runtime alloc allowed) ------
__device__ float g_votes[(size_t)BATCH * 1024 * 1024];
__device__ float g_pooled[(size_t)BATCH * COUT * 2 * DOUT * SS * SS];
__device__ float g_routed[(size_t)BATCH * COUT * DOUT * SS * SS];
__device__ float g_graw[(size_t)BATCH * COUT * DOUT * SS * SS];
__device__ double g_bnsum[COUT];
__device__ double g_bnsq[COUT];
__device__ float  g_bnmu[COUT];
__device__ float  g_bninv[COUT];

// ---------------- kernel 0: zero BN accumulators --------------------------
__global__ void k_zero_bn() {
    int i = threadIdx.x;
    if (i < COUT) { g_bnsum[i] = 0.0; g_bnsq[i] = 0.0; }
}

// ---------------- kernel 1: 3x3 conv (16 -> 1024 ch), pad 1 ---------------
// CTA = (oc_chunk of 64, batch). 256 threads, 2 CTAs/SM.
// smem: padded input [16][34][36-pitch], transposed weights [144][64], bias.
#define CONV_OC   64
#define IN_RS     36
#define IN_PLANE  (34 * IN_RS)          // 1224
#define SM_IN_F   (16 * IN_PLANE)       // 19584 floats
#define SM_W_F    (144 * CONV_OC)       // 9216 floats
#define CONV_SMEM ((SM_IN_F + SM_W_F + CONV_OC) * 4)   // 115456 B

__global__ __launch_bounds__(256, 2) void k_conv(
    const float* __restrict__ caps,
    const float* __restrict__ Wt,
    const float* __restrict__ bt)
{
    extern __shared__ float sm[];
    float* smin = sm;
    float* smw  = sm + SM_IN_F;
    float* smb  = smw + SM_W_F;

    int b = blockIdx.y;
    int oc_base = blockIdx.x * CONV_OC;
    int tid = threadIdx.x;

    // load input with zero padding (pitch 36 keeps rows 16B-aligned)
    const float* cin = caps + (size_t)b * (DIN * SS * SS);
    for (int idx = tid; idx < 16 * 34 * 34; idx += 256) {
        int ch = idx / (34 * 34);
        int r  = (idx / 34) % 34;
        int c  = idx % 34;
        float v = 0.f;
        if (r >= 1 && r <= 32 && c >= 1 && c <= 32)
            v = cin[ch * 1024 + (r - 1) * 32 + (c - 1)];
        smin[ch * IN_PLANE + r * IN_RS + c] = v;
    }
    for (int idx = tid; idx < SM_W_F; idx += 256) {
        int t = idx >> 6;
        int ocl = idx & 63;
        smw[idx] = Wt[(size_t)(oc_base + ocl) * 144 + t];
    }
    if (tid < CONV_OC) smb[tid] = bt[oc_base + tid];
    __syncthreads();

    int ocg  = tid >> 5;           // warp id 0..7 -> 8 oc per warp
    int lane = tid & 31;
    int x0   = (lane & 3) * 8;     // 8-px strip base
    int ysub = lane >> 2;          // 0..7

    const float4* smw4 = (const float4*)smw;
    float bias[8];
#pragma unroll
    for (int oo = 0; oo < 8; oo++) bias[oo] = smb[ocg * 8 + oo];

    for (int ystep = 0; ystep < 4; ystep++) {
        int y = ystep * 8 + ysub;
        float acc[8][8];
#pragma unroll
        for (int oo = 0; oo < 8; oo++)
#pragma unroll
            for (int j = 0; j < 8; j++) acc[oo][j] = 0.f;

#pragma unroll 2
        for (int ic = 0; ic < 16; ic++) {
#pragma unroll
            for (int ky = 0; ky < 3; ky++) {
                const float* rp = &smin[ic * IN_PLANE + (y + ky) * IN_RS + x0];
                float in10[10];
                float4 t0 = *(const float4*)rp;
                float4 t1 = *(const float4*)(rp + 4);
                in10[0] = t0.x; in10[1] = t0.y; in10[2] = t0.z; in10[3] = t0.w;
                in10[4] = t1.x; in10[5] = t1.y; in10[6] = t1.z; in10[7] = t1.w;
                in10[8] = rp[8]; in10[9] = rp[9];
#pragma unroll
                for (int kx = 0; kx < 3; kx++) {
                    int t = ic * 9 + ky * 3 + kx;
                    float4 wa = smw4[t * 16 + ocg * 2];
                    float4 wb = smw4[t * 16 + ocg * 2 + 1];
#pragma unroll
                    for (int j = 0; j < 8; j++) {
                        float iv = in10[kx + j];
                        acc[0][j] += wa.x * iv;
                        acc[1][j] += wa.y * iv;
                        acc[2][j] += wa.z * iv;
                        acc[3][j] += wa.w * iv;
                        acc[4][j] += wb.x * iv;
                        acc[5][j] += wb.y * iv;
                        acc[6][j] += wb.z * iv;
                        acc[7][j] += wb.w * iv;
                    }
                }
            }
        }
#pragma unroll
        for (int oo = 0; oo < 8; oo++) {
            int oc = oc_base + ocg * 8 + oo;
            float bv = bias[oo];
            float* op = &g_votes[((size_t)b * 1024 + oc) * 1024 + y * 32 + x0];
            float4 r0, r1;
            r0.x = acc[oo][0] + bv; r0.y = acc[oo][1] + bv;
            r0.z = acc[oo][2] + bv; r0.w = acc[oo][3] + bv;
            r1.x = acc[oo][4] + bv; r1.y = acc[oo][5] + bv;
            r1.z = acc[oo][6] + bv; r1.w = acc[oo][7] + bv;
            *(float4*)op = r0;
            *(float4*)(op + 4) = r1;
        }
    }
}

// ---------------- kernel 2: einsum + pooling + routing ---------------------
__global__ __launch_bounds__(256) void k_values(
    const float* __restrict__ Wv,
    const float* __restrict__ bv)
{
    __shared__ float sWv[256];   // 32 m x 8 c
    __shared__ float sbv[32];
    int b = blockIdx.z, o = blockIdx.y;
    int s = blockIdx.x * 256 + threadIdx.x;
    sWv[threadIdx.x] = Wv[o * 256 + threadIdx.x];
    if (threadIdx.x < 32) sbv[threadIdx.x] = bv[o * 32 + threadIdx.x];
    __syncthreads();

    const float* vb = g_votes + (size_t)b * 1048576 + (size_t)o * 16384 + s;
    size_t pbase = ((size_t)b * 8 + o) * 32768;
    size_t rbase = ((size_t)b * 8 + o) * 16384;

    for (int d = 0; d < 16; d++) {
        float vc[8];
#pragma unroll
        for (int c = 0; c < 8; c++) vc[c] = vb[(size_t)(c * 128 + d) * 1024];

        float pmax = -3.0e38f, psum = 0.f;
        float mcin[8], li[8];
#pragma unroll
        for (int cin = 0; cin < 8; cin++) {
            float vals[4];
#pragma unroll
            for (int kc = 0; kc < 4; kc++) {
                int m = kc * 8 + cin;
                float a = sbv[m];
#pragma unroll
                for (int c = 0; c < 8; c++) a += sWv[m * 8 + c] * vc[c];
                vals[kc] = a;
                pmax = fmaxf(pmax, a);
                psum += a;
            }
            float mn = 0.25f * (vals[0] + vals[1] + vals[2] + vals[3]);
            float d0 = vals[0] - mn, d1 = vals[1] - mn, d2 = vals[2] - mn, d3 = vals[3] - mn;
            float var = 0.25f * (d0 * d0 + d1 * d1 + d2 * d2 + d3 * d3);
            float sd = sqrtf(var);
            mcin[cin] = mn;
            li[cin] = -logf(fmaxf(sd, 1e-30f));
        }
        float mx = li[0];
#pragma unroll
        for (int c = 1; c < 8; c++) mx = fmaxf(mx, li[c]);
        float sum = 0.f, r = 0.f;
#pragma unroll
        for (int c = 0; c < 8; c++) {
            float e = expf(li[c] - mx);
            sum += e;
            r += e * mcin[c];
        }
        r /= sum;

        g_pooled[pbase + d * 1024 + s]         = pmax;
        g_pooled[pbase + 16384 + d * 1024 + s] = psum * (1.f / 32.f);
        g_routed[rbase + d * 1024 + s]         = r;
    }
}

// ---------------- kernel 3: 3x3x3 gate conv + BN (padded smem, no branches)
#define GP_PITCH 36
#define GP_PLANE (34 * GP_PITCH)     // 1224
#define GP_CH    (18 * GP_PLANE)     // 22032
#define GP_TOT   (2 * GP_CH)         // 44064 floats = 176256 B
#define GATE_SMEM (GP_TOT * 4)

__global__ __launch_bounds__(512, 1) void k_gate(const float* __restrict__ Ws)
{
    extern __shared__ float sp[];
    __shared__ float sws[54];
    __shared__ double redA[16], redB[16];
    int blk = blockIdx.x;
    int o = blk & 7;
    int tid = threadIdx.x;

    for (int i = tid; i < GP_TOT; i += 512) sp[i] = 0.f;
    if (tid < 54) sws[tid] = Ws[tid];
    __syncthreads();

    const float* src = g_pooled + (size_t)blk * 32768;
    for (int i = tid; i < 32768; i += 512) {
        int v = i & 31, u = (i >> 5) & 31, d = (i >> 10) & 15, p = i >> 14;
        sp[p * GP_CH + (d + 1) * GP_PLANE + (u + 1) * GP_PITCH + (v + 1)] = src[i];
    }
    __syncthreads();

    double ls = 0.0, lq = 0.0;
    for (int k = 0; k < 8; k++) {
        int q = k * 512 + tid;          // quad index: d*256 + u*8 + vq
        int v0 = (q & 7) * 4;
        int u  = (q >> 3) & 31;
        int d  = q >> 8;
        float a0 = 0.f, a1 = 0.f, a2 = 0.f, a3 = 0.f;
#pragma unroll
        for (int p = 0; p < 2; p++) {
#pragma unroll
            for (int kd = 0; kd < 3; kd++) {
#pragma unroll
                for (int ku = 0; ku < 3; ku++) {
                    const float* rp = &sp[p * GP_CH + (d + kd) * GP_PLANE +
                                          (u + ku) * GP_PITCH + v0];
                    float4 f = *(const float4*)rp;
                    float i4 = rp[4], i5 = rp[5];
                    const float* w = &sws[p * 27 + kd * 9 + ku * 3];
                    float w0 = w[0], w1 = w[1], w2 = w[2];
                    a0 += w0 * f.x + w1 * f.y + w2 * f.z;
                    a1 += w0 * f.y + w1 * f.z + w2 * f.w;
                    a2 += w0 * f.z + w1 * f.w + w2 * i4;
                    a3 += w0 * f.w + w1 * i4 + w2 * i5;
                }
            }
        }
        float4 r; r.x = a0; r.y = a1; r.z = a2; r.w = a3;
        *(float4*)&g_graw[(size_t)blk * 16384 + (size_t)q * 4] = r;
        ls += (double)(a0 + a1 + a2 + a3);
        lq += (double)a0 * a0 + (double)a1 * a1 + (double)a2 * a2 + (double)a3 * a3;
    }

    for (int off = 16; off; off >>= 1) {
        ls += __shfl_down_sync(0xffffffffu, ls, off);
        lq += __shfl_down_sync(0xffffffffu, lq, off);
    }
    int wid = tid >> 5, lane = tid & 31;
    if (lane == 0) { redA[wid] = ls; redB[wid] = lq; }
    __syncthreads();
    if (tid < 32) {
        double a = (tid < 16) ? redA[tid] : 0.0;
        double qq = (tid < 16) ? redB[tid] : 0.0;
        for (int off = 8; off; off >>= 1) {
            a += __shfl_down_sync(0xffffffffu, a, off);
            qq += __shfl_down_sync(0xffffffffu, qq, off);
        }
        if (tid == 0) {
            atomicAdd(&g_bnsum[o], a);
            atomicAdd(&g_bnsq[o], qq);
        }
    }
}

// ---------------- kernel 4: BN finalize ------------------------------------
__global__ void k_bnfin() {
    int o = threadIdx.x;
    if (o < COUT) {
        double N = (double)BATCH * DOUT * SS * SS;
        double mu = g_bnsum[o] / N;
        double var = g_bnsq[o] / N - mu * mu;
        g_bnmu[o]  = (float)mu;
        g_bninv[o] = (float)(1.0 / sqrt(var + (double)EPSV));
    }
}

// ---------------- kernel 5: scale + LayerNorm + transposed store -----------
__global__ __launch_bounds__(512) void k_final(
    const float* __restrict__ bng, const float* __restrict__ bnb,
    const float* __restrict__ lng, const float* __restrict__ lnb,
    float* __restrict__ out)
{
    __shared__ double redA[16], redB[16];
    __shared__ float bc[2];
    int blk = blockIdx.x;
    int b = blk >> 3, o = blk & 7;
    int tid = threadIdx.x;

    float mu = g_bnmu[o], inv = g_bninv[o];
    float ga = bng[0], be = bnb[0];
    const float* gr = g_graw   + (size_t)blk * 16384;
    const float* rt = g_routed + (size_t)blk * 16384;

    float xv[32];
    double ls = 0.0, lq = 0.0;
#pragma unroll
    for (int k = 0; k < 32; k++) {
        int i = k * 512 + tid;
        float g = (gr[i] - mu) * inv * ga + be;
        float sc = 1.f / (1.f + expf(-g));
        float x = rt[i] * (1.f + sc);
        xv[k] = x;
        ls += x;
        lq += (double)x * x;
    }
    for (int off = 16; off; off >>= 1) {
        ls += __shfl_down_sync(0xffffffffu, ls, off);
        lq += __shfl_down_sync(0xffffffffu, lq, off);
    }
    int wid = tid >> 5, lane = tid & 31;
    if (lane == 0) { redA[wid] = ls; redB[wid] = lq; }
    __syncthreads();
    if (tid < 32) {
        double a = (tid < 16) ? redA[tid] : 0.0;
        double q = (tid < 16) ? redB[tid] : 0.0;
        for (int off = 8; off; off >>= 1) {
            a += __shfl_down_sync(0xffffffffu, a, off);
            q += __shfl_down_sync(0xffffffffu, q, off);
        }
        if (tid == 0) {
            double N = 16384.0;
            double mean = a / N;
            double var = q / N - mean * mean;
            bc[0] = (float)mean;
            bc[1] = (float)(1.0 / sqrt(var + (double)EPSV));
        }
    }
    __syncthreads();
    float mean = bc[0], rstd = bc[1];
    float* ob = out + ((size_t)o * BATCH + b) * 16384;
#pragma unroll
    for (int k = 0; k < 32; k++) {
        int i = k * 512 + tid;
        ob[i] = (xv[k] - mean) * rstd * lng[i] + lnb[i];
    }
}

// ---------------- launch ----------------------------------------------------
extern "C" void kernel_launch(void* const* d_in, const int* in_sizes, int n_in,
                              void* d_out, int out_size)
{
    const float* caps = (const float*)d_in[0];
    const float* Wt   = (const float*)d_in[1];
    const float* bt   = (const float*)d_in[2];
    const float* Wv   = (const float*)d_in[3];
    const float* bv   = (const float*)d_in[4];
    const float* Ws   = (const float*)d_in[5];
    const float* bng  = (const float*)d_in[6];
    const float* bnb  = (const float*)d_in[7];
    const float* lng  = (const float*)d_in[8];
    const float* lnb  = (const float*)d_in[9];
    float* out = (float*)d_out;

    cudaFuncSetAttribute(k_conv, cudaFuncAttributeMaxDynamicSharedMemorySize, CONV_SMEM);
    cudaFuncSetAttribute(k_gate, cudaFuncAttributeMaxDynamicSharedMemorySize, GATE_SMEM);

    k_zero_bn<<<1, 32>>>();

    dim3 gconv(1024 / CONV_OC, BATCH);
    k_conv<<<gconv, 256, CONV_SMEM>>>(caps, Wt, bt);

    dim3 gval(4, COUT, BATCH);
    k_values<<<gval, 256>>>(Wv, bv);

    k_gate<<<BATCH * COUT, 512, GATE_SMEM>>>(Ws);

    k_bnfin<<<1, 8>>>();

    k_final<<<BATCH * COUT, 512>>>(bng, bnb, lng, lnb, out);

    (void)in_sizes; (void)n_in; (void)out_size;
}